// round 1
// baseline (speedup 1.0000x reference)
#include <cuda_runtime.h>
#include <math.h>

#define Bsz   2
#define Ls    2048
#define Cdim  1024
#define NH    16
#define HD    64
#define HARM  32
#define TOK   (Bsz*Ls)   // 4096

// ---------------- device scratch (allocation-free rule: __device__ globals) ----------
__device__ float g_w[4][HARM*Cdim];      // w transposed: [h][o]
__device__ float g_Bt[Cdim*96];          // stacked qkv basis, transposed: [i][j], j in 0..95
__device__ float g_BoT[Cdim*HARM];       // basis_o transposed: [i][h]
__device__ float g_R[TOK*96];            // qkv resonances
__device__ float g_qkv[3][TOK*Cdim];     // q, k, v in [B,L,C] layout
__device__ float g_att[TOK*Cdim];        // attention output [B,L,C]
__device__ float g_Ro[TOK*HARM];         // output-projection resonance

// Swizzled smem addressing: 64-float rows, XOR the float4-chunk index with (row>>2).
// Guarantees conflict-free float4 column/row access patterns used below.
#define SWZ(row, col) (((row)<<6) + ((((((col)>>2)) ^ ((row)>>2)) & 15)<<2) + ((col)&3))

// ---------------- kernel 1: w = amp * cos(phase), stored transposed [h][o] ----------
__global__ void k_w(const float* __restrict__ pq, const float* __restrict__ aq,
                    const float* __restrict__ pk, const float* __restrict__ ak,
                    const float* __restrict__ pv, const float* __restrict__ av,
                    const float* __restrict__ po, const float* __restrict__ ao) {
    int i = blockIdx.x * blockDim.x + threadIdx.x;  // 0..32767, i = o*32 + h
    int o = i >> 5, h = i & 31;
    int j = h * Cdim + o;
    g_w[0][j] = aq[i] * cosf(pq[i]);
    g_w[1][j] = ak[i] * cosf(pk[i]);
    g_w[2][j] = av[i] * cosf(pv[i]);
    g_w[3][j] = ao[i] * cosf(po[i]);
}

// ---------------- kernel 2: transpose + stack bases ---------------------------------
__global__ void k_tr(const float* __restrict__ bq, const float* __restrict__ bk,
                     const float* __restrict__ bv, const float* __restrict__ bo) {
    int i = blockIdx.x * blockDim.x + threadIdx.x;  // 0..32767, i = h*1024 + d
    int h = i >> 10, d = i & 1023;
    g_Bt[d*96 + h]      = bq[i];
    g_Bt[d*96 + 32 + h] = bk[i];
    g_Bt[d*96 + 64 + h] = bv[i];
    g_BoT[d*32 + h]     = bo[i];
}

// ---------------- kernel 3: R = x @ Bt  ([4096,1024] x [1024,96]) -------------------
__global__ void __launch_bounds__(384) k_res96(const float* __restrict__ x) {
    __shared__ float xs[8][1024];
    int t0 = blockIdx.x * 8;
    const float4* xg = (const float4*)(x + (size_t)t0 * Cdim);
    float4* s4 = (float4*)xs;
    for (int i = threadIdx.x; i < 2048; i += 384) s4[i] = xg[i];
    __syncthreads();
    int j  = threadIdx.x % 96;
    int tg = threadIdx.x / 96;       // 0..3, two tokens each
    float acc0 = 0.f, acc1 = 0.f;
    const float* xr0 = xs[tg*2];
    const float* xr1 = xs[tg*2+1];
    #pragma unroll 8
    for (int i = 0; i < 1024; i++) {
        float b = g_Bt[i*96 + j];
        acc0 += xr0[i] * b;
        acc1 += xr1[i] * b;
    }
    g_R[(size_t)(t0 + tg*2    )*96 + j] = acc0;
    g_R[(size_t)(t0 + tg*2 + 1)*96 + j] = acc1;
}

// ---------------- kernel 6: Ro = att @ BoT ([4096,1024] x [1024,32]) ----------------
__global__ void __launch_bounds__(256) k_res32() {
    __shared__ float xs[8][1024];
    int t0 = blockIdx.x * 8;
    const float4* xg = (const float4*)(g_att + (size_t)t0 * Cdim);
    float4* s4 = (float4*)xs;
    for (int i = threadIdx.x; i < 2048; i += 256) s4[i] = xg[i];
    __syncthreads();
    int h  = threadIdx.x & 31;
    int tg = threadIdx.x >> 5;       // 0..7, one token each
    float acc = 0.f;
    const float* xr = xs[tg];
    #pragma unroll 8
    for (int i = 0; i < 1024; i++) acc += xr[i] * g_BoT[i*32 + h];
    g_Ro[(size_t)(t0 + tg)*32 + h] = acc;
}

// ---------------- kernel 4/7: expand resonance: out[t][c] = sum_h R[t][h] * w[h][c] -
// which: 0/1/2 -> q/k/v from g_R (col offset which*32); 3 -> final out from g_Ro.
__global__ void __launch_bounds__(256) k_proj(int which, float* __restrict__ dout) {
    __shared__ float Rs[16][32];
    int t0 = blockIdx.x * 16;
    int tid = threadIdx.x;
    const float* Rsrc; int rstride, roff; const float* w; float* out;
    if (which < 3) { Rsrc = g_R;  rstride = 96; roff = which*32; w = g_w[which]; out = g_qkv[which]; }
    else           { Rsrc = g_Ro; rstride = 32; roff = 0;        w = g_w[3];     out = dout; }

    for (int i = tid; i < 512; i += 256) {
        int t = i >> 5, h = i & 31;
        Rs[t][h] = Rsrc[(size_t)(t0 + t)*rstride + roff + h];
    }
    __syncthreads();

    float acc[16][4];
    #pragma unroll
    for (int t = 0; t < 16; t++)
        #pragma unroll
        for (int j = 0; j < 4; j++) acc[t][j] = 0.f;

    #pragma unroll
    for (int h = 0; h < 32; h++) {
        float w0 = w[h*Cdim + tid      ];
        float w1 = w[h*Cdim + tid + 256];
        float w2 = w[h*Cdim + tid + 512];
        float w3 = w[h*Cdim + tid + 768];
        #pragma unroll
        for (int t = 0; t < 16; t++) {
            float r = Rs[t][h];
            acc[t][0] += r * w0;
            acc[t][1] += r * w1;
            acc[t][2] += r * w2;
            acc[t][3] += r * w3;
        }
    }
    #pragma unroll
    for (int t = 0; t < 16; t++) {
        float* op = out + (size_t)(t0 + t)*Cdim;
        op[tid      ] = acc[t][0];
        op[tid + 256] = acc[t][1];
        op[tid + 512] = acc[t][2];
        op[tid + 768] = acc[t][3];
    }
}

// ---------------- kernel 5: flash attention, fp32, 64-query tiles -------------------
// grid (L/64, B*H), 256 threads. Thread (ty,tx) owns 4x4 tile of [64 q x 64 k] scores
// and 4x4 of the [64 q x 64 d] output accumulator.
__global__ void __launch_bounds__(256, 2) k_attn() {
    extern __shared__ float smem[];
    float* Qs  = smem;            // [r][d] natural, swizzled   (16KB)
    float* Kst = smem + 4096;     // [d][c] transposed, swizzled(16KB)
    float* Vs  = smem + 8192;     // [kl][d] natural, swizzled  (16KB)
    float* Ps  = smem + 12288;    // [r][c] natural, swizzled   (16KB)

    int qt = blockIdx.x;          // query tile 0..31
    int bh = blockIdx.y;          // 0..31
    int b = bh >> 4, h = bh & 15;
    const float* __restrict__ Qg = g_qkv[0] + (size_t)b*Ls*Cdim + h*HD;
    const float* __restrict__ Kg = g_qkv[1] + (size_t)b*Ls*Cdim + h*HD;
    const float* __restrict__ Vg = g_qkv[2] + (size_t)b*Ls*Cdim + h*HD;
    float* __restrict__ Og = g_att + (size_t)b*Ls*Cdim + h*HD;

    int tid = threadIdx.x;
    int ty = tid >> 4, tx = tid & 15;
    const float scale = 0.125f;   // 64^-0.5

    // Load Q tile, pre-scaled. 1024 float4 total.
    for (int i = tid; i < 1024; i += 256) {
        int r = i >> 4, f4 = i & 15;
        float4 v = *(const float4*)(Qg + (size_t)(qt*64 + r)*Cdim + f4*4);
        v.x *= scale; v.y *= scale; v.z *= scale; v.w *= scale;
        *(float4*)&Qs[SWZ(r, f4*4)] = v;
    }

    float m[4], l[4], O[4][4];
    #pragma unroll
    for (int i = 0; i < 4; i++) {
        m[i] = -1e30f; l[i] = 0.f;
        #pragma unroll
        for (int j = 0; j < 4; j++) O[i][j] = 0.f;
    }

    for (int kt = 0; kt < 32; kt++) {
        __syncthreads();   // prior PV readers done before K/V overwrite
        for (int i = tid; i < 1024; i += 256) {
            int r = i >> 4, f4 = i & 15;
            float4 kv = *(const float4*)(Kg + (size_t)(kt*64 + r)*Cdim + f4*4);
            Kst[SWZ(f4*4 + 0, r)] = kv.x;
            Kst[SWZ(f4*4 + 1, r)] = kv.y;
            Kst[SWZ(f4*4 + 2, r)] = kv.z;
            Kst[SWZ(f4*4 + 3, r)] = kv.w;
            float4 vv = *(const float4*)(Vg + (size_t)(kt*64 + r)*Cdim + f4*4);
            *(float4*)&Vs[SWZ(r, f4*4)] = vv;
        }
        __syncthreads();

        // ---- S = Qs . Kst^T (per-thread 4x4) ----
        float S[4][4];
        #pragma unroll
        for (int i = 0; i < 4; i++)
            #pragma unroll
            for (int j = 0; j < 4; j++) S[i][j] = 0.f;

        #pragma unroll 4
        for (int dg = 0; dg < 16; dg++) {
            int qoff = ((dg ^ ty) & 15) * 4;
            int boff = ((tx ^ dg) & 15) * 4;
            #pragma unroll
            for (int dd = 0; dd < 4; dd++) {
                int d = dg*4 + dd;
                float a0 = Qs[(ty*4 + 0)*64 + qoff + dd];
                float a1 = Qs[(ty*4 + 1)*64 + qoff + dd];
                float a2 = Qs[(ty*4 + 2)*64 + qoff + dd];
                float a3 = Qs[(ty*4 + 3)*64 + qoff + dd];
                float4 bv = *(const float4*)&Kst[d*64 + boff];
                S[0][0] += a0*bv.x; S[0][1] += a0*bv.y; S[0][2] += a0*bv.z; S[0][3] += a0*bv.w;
                S[1][0] += a1*bv.x; S[1][1] += a1*bv.y; S[1][2] += a1*bv.z; S[1][3] += a1*bv.w;
                S[2][0] += a2*bv.x; S[2][1] += a2*bv.y; S[2][2] += a2*bv.z; S[2][3] += a2*bv.w;
                S[3][0] += a3*bv.x; S[3][1] += a3*bv.y; S[3][2] += a3*bv.z; S[3][3] += a3*bv.w;
            }
        }

        // ---- online softmax update (row reductions across the 16 tx lanes) ----
        #pragma unroll
        for (int i = 0; i < 4; i++) {
            float rm = fmaxf(fmaxf(S[i][0], S[i][1]), fmaxf(S[i][2], S[i][3]));
            rm = fmaxf(rm, __shfl_xor_sync(0xffffffffu, rm, 1, 16));
            rm = fmaxf(rm, __shfl_xor_sync(0xffffffffu, rm, 2, 16));
            rm = fmaxf(rm, __shfl_xor_sync(0xffffffffu, rm, 4, 16));
            rm = fmaxf(rm, __shfl_xor_sync(0xffffffffu, rm, 8, 16));
            float mn = fmaxf(m[i], rm);
            float alpha = __expf(m[i] - mn);
            m[i] = mn;
            float rs = 0.f;
            #pragma unroll
            for (int j = 0; j < 4; j++) {
                float p = __expf(S[i][j] - mn);
                S[i][j] = p;
                rs += p;
            }
            rs += __shfl_xor_sync(0xffffffffu, rs, 1, 16);
            rs += __shfl_xor_sync(0xffffffffu, rs, 2, 16);
            rs += __shfl_xor_sync(0xffffffffu, rs, 4, 16);
            rs += __shfl_xor_sync(0xffffffffu, rs, 8, 16);
            l[i] = l[i]*alpha + rs;
            #pragma unroll
            for (int j = 0; j < 4; j++) O[i][j] *= alpha;
        }

        // store P (row-major, float4 per row -> conflict-free)
        #pragma unroll
        for (int i = 0; i < 4; i++) {
            float4 p4 = make_float4(S[i][0], S[i][1], S[i][2], S[i][3]);
            *(float4*)&Ps[SWZ(ty*4 + i, tx*4)] = p4;
        }
        __syncthreads();

        // ---- O += P . V ----
        #pragma unroll 4
        for (int kg = 0; kg < 16; kg++) {
            int poff = ((kg ^ ty) & 15) * 4;
            int voff = ((tx ^ kg) & 15) * 4;
            #pragma unroll
            for (int kk = 0; kk < 4; kk++) {
                int kl = kg*4 + kk;
                float a0 = Ps[(ty*4 + 0)*64 + poff + kk];
                float a1 = Ps[(ty*4 + 1)*64 + poff + kk];
                float a2 = Ps[(ty*4 + 2)*64 + poff + kk];
                float a3 = Ps[(ty*4 + 3)*64 + poff + kk];
                float4 bv = *(const float4*)&Vs[kl*64 + voff];
                O[0][0] += a0*bv.x; O[0][1] += a0*bv.y; O[0][2] += a0*bv.z; O[0][3] += a0*bv.w;
                O[1][0] += a1*bv.x; O[1][1] += a1*bv.y; O[1][2] += a1*bv.z; O[1][3] += a1*bv.w;
                O[2][0] += a2*bv.x; O[2][1] += a2*bv.y; O[2][2] += a2*bv.z; O[2][3] += a2*bv.w;
                O[3][0] += a3*bv.x; O[3][1] += a3*bv.y; O[3][2] += a3*bv.z; O[3][3] += a3*bv.w;
            }
        }
    }

    // epilogue: normalize + store (float4 per row -> coalesced)
    #pragma unroll
    for (int i = 0; i < 4; i++) {
        float inv = 1.f / l[i];
        float4 o4 = make_float4(O[i][0]*inv, O[i][1]*inv, O[i][2]*inv, O[i][3]*inv);
        *(float4*)(Og + (size_t)(qt*64 + ty*4 + i)*Cdim + tx*4) = o4;
    }
}

// ---------------- launch -------------------------------------------------------------
extern "C" void kernel_launch(void* const* d_in, const int* in_sizes, int n_in,
                              void* d_out, int out_size) {
    const float* x  = (const float*)d_in[0];
    const float* bq = (const float*)d_in[1];
    const float* pq = (const float*)d_in[2];
    const float* aq = (const float*)d_in[3];
    const float* bk = (const float*)d_in[4];
    const float* pk = (const float*)d_in[5];
    const float* ak = (const float*)d_in[6];
    const float* bv = (const float*)d_in[7];
    const float* pv = (const float*)d_in[8];
    const float* av = (const float*)d_in[9];
    const float* bo = (const float*)d_in[10];
    const float* po = (const float*)d_in[11];
    const float* ao = (const float*)d_in[12];
    float* out = (float*)d_out;

    static bool attr_set = false;
    if (!attr_set) {
        cudaFuncSetAttribute(k_attn, cudaFuncAttributeMaxDynamicSharedMemorySize, 65536);
        attr_set = true;
    }

    k_w  <<<128, 256>>>(pq, aq, pk, ak, pv, av, po, ao);
    k_tr <<<128, 256>>>(bq, bk, bv, bo);
    k_res96<<<TOK/8, 384>>>(x);
    k_proj<<<TOK/16, 256>>>(0, out);
    k_proj<<<TOK/16, 256>>>(1, out);
    k_proj<<<TOK/16, 256>>>(2, out);
    k_attn<<<dim3(Ls/64, Bsz*NH), 256, 65536>>>();
    k_res32<<<TOK/8, 256>>>();
    k_proj<<<TOK/16, 256>>>(3, out);
}

// round 3
// speedup vs baseline: 2.0037x; 2.0037x over previous
#include <cuda_runtime.h>
#include <math.h>

#define Bsz   2
#define Ls    2048
#define Cdim  1024
#define NH    16
#define HD    64
#define HARM  32
#define TOK   (Bsz*Ls)   // 4096

// ---------------- device scratch ----------------------------------------------------
__device__ float g_w[4][HARM*Cdim];      // w transposed: [h][o]
__device__ float g_Bt[Cdim*96];          // stacked qkv basis, transposed
__device__ float g_BoT[Cdim*HARM];       // basis_o transposed
__device__ float g_R[TOK*96];            // qkv resonances
__device__ float g_qkv[3][TOK*Cdim];     // q, k, v in [B,L,C] layout
__device__ float g_att[TOK*Cdim];        // attention output [B,L,C]
__device__ float g_Ro[TOK*HARM];         // output-projection resonance

__device__ __forceinline__ float f2tf32(float f) {
    unsigned r;
    asm("cvt.rna.tf32.f32 %0, %1;" : "=r"(r) : "f"(f));
    return __uint_as_float(r);
}

__device__ __forceinline__ void mma_tf32(float d[4], const unsigned a[4],
                                         unsigned b0, unsigned b1) {
    asm("mma.sync.aligned.m16n8k8.row.col.f32.tf32.tf32.f32 "
        "{%0,%1,%2,%3}, {%4,%5,%6,%7}, {%8,%9}, {%0,%1,%2,%3};"
        : "+f"(d[0]), "+f"(d[1]), "+f"(d[2]), "+f"(d[3])
        : "r"(a[0]), "r"(a[1]), "r"(a[2]), "r"(a[3]), "r"(b0), "r"(b1));
}

// ---------------- kernel 1: w = amp * cos(phase), stored transposed [h][o] ----------
__global__ void k_w(const float* __restrict__ pq, const float* __restrict__ aq,
                    const float* __restrict__ pk, const float* __restrict__ ak,
                    const float* __restrict__ pv, const float* __restrict__ av,
                    const float* __restrict__ po, const float* __restrict__ ao) {
    int i = blockIdx.x * blockDim.x + threadIdx.x;
    int o = i >> 5, h = i & 31;
    int j = h * Cdim + o;
    g_w[0][j] = aq[i] * cosf(pq[i]);
    g_w[1][j] = ak[i] * cosf(pk[i]);
    g_w[2][j] = av[i] * cosf(pv[i]);
    g_w[3][j] = ao[i] * cosf(po[i]);
}

// ---------------- kernel 2: transpose + stack bases ---------------------------------
__global__ void k_tr(const float* __restrict__ bq, const float* __restrict__ bk,
                     const float* __restrict__ bv, const float* __restrict__ bo) {
    int i = blockIdx.x * blockDim.x + threadIdx.x;
    int h = i >> 10, d = i & 1023;
    g_Bt[d*96 + h]      = bq[i];
    g_Bt[d*96 + 32 + h] = bk[i];
    g_Bt[d*96 + 64 + h] = bv[i];
    g_BoT[d*32 + h]     = bo[i];
}

// ---------------- kernel 3: R = x @ Bt  ([4096,1024] x [1024,96]) -------------------
__global__ void __launch_bounds__(384) k_res96(const float* __restrict__ x) {
    __shared__ float xs[8][1024];
    int t0 = blockIdx.x * 8;
    const float4* xg = (const float4*)(x + (size_t)t0 * Cdim);
    float4* s4 = (float4*)xs;
    for (int i = threadIdx.x; i < 2048; i += 384) s4[i] = xg[i];
    __syncthreads();
    int j  = threadIdx.x % 96;
    int tg = threadIdx.x / 96;
    float acc0 = 0.f, acc1 = 0.f;
    const float* xr0 = xs[tg*2];
    const float* xr1 = xs[tg*2+1];
    #pragma unroll 8
    for (int i = 0; i < 1024; i++) {
        float b = g_Bt[i*96 + j];
        acc0 += xr0[i] * b;
        acc1 += xr1[i] * b;
    }
    g_R[(size_t)(t0 + tg*2    )*96 + j] = acc0;
    g_R[(size_t)(t0 + tg*2 + 1)*96 + j] = acc1;
}

// ---------------- kernel 6: Ro = att @ BoT ------------------------------------------
__global__ void __launch_bounds__(256) k_res32() {
    __shared__ float xs[8][1024];
    int t0 = blockIdx.x * 8;
    const float4* xg = (const float4*)(g_att + (size_t)t0 * Cdim);
    float4* s4 = (float4*)xs;
    for (int i = threadIdx.x; i < 2048; i += 256) s4[i] = xg[i];
    __syncthreads();
    int h  = threadIdx.x & 31;
    int tg = threadIdx.x >> 5;
    float acc = 0.f;
    const float* xr = xs[tg];
    #pragma unroll 8
    for (int i = 0; i < 1024; i++) acc += xr[i] * g_BoT[i*32 + h];
    g_Ro[(size_t)(t0 + tg)*32 + h] = acc;
}

// ---------------- kernel 4/7: expand resonance --------------------------------------
__global__ void __launch_bounds__(256) k_proj(int which, float* __restrict__ dout) {
    __shared__ float Rs[16][32];
    int t0 = blockIdx.x * 16;
    int tid = threadIdx.x;
    const float* Rsrc; int rstride, roff; const float* w; float* out;
    if (which < 3) { Rsrc = g_R;  rstride = 96; roff = which*32; w = g_w[which]; out = g_qkv[which]; }
    else           { Rsrc = g_Ro; rstride = 32; roff = 0;        w = g_w[3];     out = dout; }

    for (int i = tid; i < 512; i += 256) {
        int t = i >> 5, h = i & 31;
        Rs[t][h] = Rsrc[(size_t)(t0 + t)*rstride + roff + h];
    }
    __syncthreads();

    float acc[16][4];
    #pragma unroll
    for (int t = 0; t < 16; t++)
        #pragma unroll
        for (int j = 0; j < 4; j++) acc[t][j] = 0.f;

    #pragma unroll
    for (int h = 0; h < 32; h++) {
        float w0 = w[h*Cdim + tid      ];
        float w1 = w[h*Cdim + tid + 256];
        float w2 = w[h*Cdim + tid + 512];
        float w3 = w[h*Cdim + tid + 768];
        #pragma unroll
        for (int t = 0; t < 16; t++) {
            float r = Rs[t][h];
            acc[t][0] += r * w0;
            acc[t][1] += r * w1;
            acc[t][2] += r * w2;
            acc[t][3] += r * w3;
        }
    }
    #pragma unroll
    for (int t = 0; t < 16; t++) {
        float* op = out + (size_t)(t0 + t)*Cdim;
        op[tid      ] = acc[t][0];
        op[tid + 256] = acc[t][1];
        op[tid + 512] = acc[t][2];
        op[tid + 768] = acc[t][3];
    }
}

// ---------------- kernel 5: flash attention, tf32 mma.sync --------------------------
// grid (L/128, B*H), 256 threads = 8 warps, each warp owns 16 query rows.
// Smem row stride 68 floats -> conflict-free fragment LDS patterns.
#define SST 68
__global__ void __launch_bounds__(256, 2) k_attn() {
    extern __shared__ float smem[];
    float* QPs = smem;            // [128][68]: Q tile (prologue) then P tiles (warp-local)
    float* Ks  = smem + 128*SST;  // [64][68]: K tile, [key][d]
    float* Vs  = Ks + 64*SST;     // [64][68]: V tile, [key][d]

    int qt = blockIdx.x;          // 0..15
    int bh = blockIdx.y;          // 0..31
    int b = bh >> 4, h = bh & 15;
    const float* __restrict__ Qg = g_qkv[0] + (size_t)b*Ls*Cdim + h*HD;
    const float* __restrict__ Kg = g_qkv[1] + (size_t)b*Ls*Cdim + h*HD;
    const float* __restrict__ Vg = g_qkv[2] + (size_t)b*Ls*Cdim + h*HD;
    float* __restrict__ Og = g_att + (size_t)b*Ls*Cdim + h*HD;

    int tid = threadIdx.x;
    int wid = tid >> 5, lane = tid & 31;
    int g = lane >> 2, c = lane & 3;
    int wr = wid * 16;            // warp's query-row base within tile
    const float scale = 0.125f;

    // ---- prologue: Q tile -> smem (scaled, tf32-rounded), then to register frags ----
    for (int i = tid; i < 2048; i += 256) {         // 128 rows x 16 float4
        int r = i >> 4, f4 = i & 15;
        float4 v = *(const float4*)(Qg + (size_t)(qt*128 + r)*Cdim + f4*4);
        float* dst = &QPs[r*SST + f4*4];
        dst[0] = f2tf32(v.x*scale); dst[1] = f2tf32(v.y*scale);
        dst[2] = f2tf32(v.z*scale); dst[3] = f2tf32(v.w*scale);
    }
    __syncthreads();

    unsigned qf[8][4];
    #pragma unroll
    for (int kg = 0; kg < 8; kg++) {
        qf[kg][0] = __float_as_uint(QPs[(wr+g  )*SST + kg*8 + c    ]);
        qf[kg][1] = __float_as_uint(QPs[(wr+g+8)*SST + kg*8 + c    ]);
        qf[kg][2] = __float_as_uint(QPs[(wr+g  )*SST + kg*8 + c + 4]);
        qf[kg][3] = __float_as_uint(QPs[(wr+g+8)*SST + kg*8 + c + 4]);
    }

    float m0 = -1e30f, m1 = -1e30f, l0 = 0.f, l1 = 0.f;
    float O[8][4];
    #pragma unroll
    for (int nt = 0; nt < 8; nt++)
        #pragma unroll
        for (int j = 0; j < 4; j++) O[nt][j] = 0.f;

    for (int kt = 0; kt < 32; kt++) {
        __syncthreads();   // prior-iteration readers of Ks/Vs (and Qs frag loads) done
        for (int i = tid; i < 1024; i += 256) {     // 64 rows x 16 float4, K and V
            int r = i >> 4, f4 = i & 15;
            float4 kv = *(const float4*)(Kg + (size_t)(kt*64 + r)*Cdim + f4*4);
            float* kd = &Ks[r*SST + f4*4];
            kd[0] = f2tf32(kv.x); kd[1] = f2tf32(kv.y);
            kd[2] = f2tf32(kv.z); kd[3] = f2tf32(kv.w);
            float4 vv = *(const float4*)(Vg + (size_t)(kt*64 + r)*Cdim + f4*4);
            float* vd = &Vs[r*SST + f4*4];
            vd[0] = f2tf32(vv.x); vd[1] = f2tf32(vv.y);
            vd[2] = f2tf32(vv.z); vd[3] = f2tf32(vv.w);
        }
        __syncthreads();

        // ---- S = Q . K^T : 8 n-tiles (keys) x 8 k-groups (head dim) ----
        float S[8][4];
        #pragma unroll
        for (int nt = 0; nt < 8; nt++)
            #pragma unroll
            for (int j = 0; j < 4; j++) S[nt][j] = 0.f;

        #pragma unroll
        for (int kg = 0; kg < 8; kg++) {
            #pragma unroll
            for (int nt = 0; nt < 8; nt++) {
                unsigned b0 = __float_as_uint(Ks[(nt*8+g)*SST + kg*8 + c    ]);
                unsigned b1 = __float_as_uint(Ks[(nt*8+g)*SST + kg*8 + c + 4]);
                mma_tf32(S[nt], qf[kg], b0, b1);
            }
        }

        // ---- online softmax (rows wr+g and wr+g+8) ----
        float mx0 = -1e30f, mx1 = -1e30f;
        #pragma unroll
        for (int nt = 0; nt < 8; nt++) {
            mx0 = fmaxf(mx0, fmaxf(S[nt][0], S[nt][1]));
            mx1 = fmaxf(mx1, fmaxf(S[nt][2], S[nt][3]));
        }
        mx0 = fmaxf(mx0, __shfl_xor_sync(0xffffffffu, mx0, 1));
        mx0 = fmaxf(mx0, __shfl_xor_sync(0xffffffffu, mx0, 2));
        mx1 = fmaxf(mx1, __shfl_xor_sync(0xffffffffu, mx1, 1));
        mx1 = fmaxf(mx1, __shfl_xor_sync(0xffffffffu, mx1, 2));

        float mn0 = fmaxf(m0, mx0), mn1 = fmaxf(m1, mx1);
        float a0 = __expf(m0 - mn0), a1 = __expf(m1 - mn1);
        m0 = mn0; m1 = mn1;

        float s0 = 0.f, s1 = 0.f;
        #pragma unroll
        for (int nt = 0; nt < 8; nt++) {
            S[nt][0] = __expf(S[nt][0] - mn0); s0 += S[nt][0];
            S[nt][1] = __expf(S[nt][1] - mn0); s0 += S[nt][1];
            S[nt][2] = __expf(S[nt][2] - mn1); s1 += S[nt][2];
            S[nt][3] = __expf(S[nt][3] - mn1); s1 += S[nt][3];
        }
        s0 += __shfl_xor_sync(0xffffffffu, s0, 1);
        s0 += __shfl_xor_sync(0xffffffffu, s0, 2);
        s1 += __shfl_xor_sync(0xffffffffu, s1, 1);
        s1 += __shfl_xor_sync(0xffffffffu, s1, 2);
        l0 = l0*a0 + s0;
        l1 = l1*a1 + s1;
        #pragma unroll
        for (int nt = 0; nt < 8; nt++) {
            O[nt][0] *= a0; O[nt][1] *= a0;
            O[nt][2] *= a1; O[nt][3] *= a1;
        }

        // ---- store P (warp-local rows of QPs), tf32-rounded ----
        #pragma unroll
        for (int nt = 0; nt < 8; nt++) {
            QPs[(wr+g  )*SST + nt*8 + 2*c    ] = f2tf32(S[nt][0]);
            QPs[(wr+g  )*SST + nt*8 + 2*c + 1] = f2tf32(S[nt][1]);
            QPs[(wr+g+8)*SST + nt*8 + 2*c    ] = f2tf32(S[nt][2]);
            QPs[(wr+g+8)*SST + nt*8 + 2*c + 1] = f2tf32(S[nt][3]);
        }
        __syncwarp();

        // ---- O += P . V ----
        #pragma unroll
        for (int kg = 0; kg < 8; kg++) {
            unsigned pf[4];
            pf[0] = __float_as_uint(QPs[(wr+g  )*SST + kg*8 + c    ]);
            pf[1] = __float_as_uint(QPs[(wr+g+8)*SST + kg*8 + c    ]);
            pf[2] = __float_as_uint(QPs[(wr+g  )*SST + kg*8 + c + 4]);
            pf[3] = __float_as_uint(QPs[(wr+g+8)*SST + kg*8 + c + 4]);
            #pragma unroll
            for (int nt = 0; nt < 8; nt++) {
                unsigned b0 = __float_as_uint(Vs[(kg*8 + c    )*SST + nt*8 + g]);
                unsigned b1 = __float_as_uint(Vs[(kg*8 + c + 4)*SST + nt*8 + g]);
                mma_tf32(O[nt], pf, b0, b1);
            }
        }
        __syncwarp();   // PV reads done before next-iteration P overwrite
    }

    // ---- epilogue ----
    float i0 = 1.f / l0, i1 = 1.f / l1;
    #pragma unroll
    for (int nt = 0; nt < 8; nt++) {
        float2 o0 = make_float2(O[nt][0]*i0, O[nt][1]*i0);
        float2 o1 = make_float2(O[nt][2]*i1, O[nt][3]*i1);
        *(float2*)(Og + (size_t)(qt*128 + wr + g    )*Cdim + nt*8 + 2*c) = o0;
        *(float2*)(Og + (size_t)(qt*128 + wr + g + 8)*Cdim + nt*8 + 2*c) = o1;
    }
}

// ---------------- launch -------------------------------------------------------------
extern "C" void kernel_launch(void* const* d_in, const int* in_sizes, int n_in,
                              void* d_out, int out_size) {
    const float* x  = (const float*)d_in[0];
    const float* bq = (const float*)d_in[1];
    const float* pq = (const float*)d_in[2];
    const float* aq = (const float*)d_in[3];
    const float* bk = (const float*)d_in[4];
    const float* pk = (const float*)d_in[5];
    const float* ak = (const float*)d_in[6];
    const float* bv = (const float*)d_in[7];
    const float* pv = (const float*)d_in[8];
    const float* av = (const float*)d_in[9];
    const float* bo = (const float*)d_in[10];
    const float* po = (const float*)d_in[11];
    const float* ao = (const float*)d_in[12];
    float* out = (float*)d_out;

    static bool attr_set = false;
    if (!attr_set) {
        cudaFuncSetAttribute(k_attn, cudaFuncAttributeMaxDynamicSharedMemorySize,
                             (128 + 64 + 64) * SST * 4);
        attr_set = true;
    }

    k_w  <<<128, 256>>>(pq, aq, pk, ak, pv, av, po, ao);
    k_tr <<<128, 256>>>(bq, bk, bv, bo);
    k_res96<<<TOK/8, 384>>>(x);
    k_proj<<<TOK/16, 256>>>(0, out);
    k_proj<<<TOK/16, 256>>>(1, out);
    k_proj<<<TOK/16, 256>>>(2, out);
    k_attn<<<dim3(Ls/128, Bsz*NH), 256, (128 + 64 + 64) * SST * 4>>>();
    k_res32<<<TOK/8, 256>>>();
    k_proj<<<TOK/16, 256>>>(3, out);
}

// round 4
// speedup vs baseline: 2.1636x; 1.0798x over previous
#include <cuda_runtime.h>
#include <math.h>

#define Bsz   2
#define Ls    2048
#define Cdim  1024
#define NH    16
#define HD    64
#define HARM  32
#define TOK   (Bsz*Ls)   // 4096

// ---------------- device scratch ----------------------------------------------------
__device__ float g_w[4][HARM*Cdim];      // w transposed: [h][o]
__device__ float g_Bt[Cdim*96];          // stacked qkv basis, transposed
__device__ float g_BoT[Cdim*HARM];       // basis_o transposed
__device__ float g_R[TOK*96];            // qkv resonances
__device__ float g_qkv[3][TOK*Cdim];     // q, k, v in [B,L,C] layout
__device__ float g_att[TOK*Cdim];        // attention output [B,L,C]
__device__ float g_Ro[TOK*HARM];         // output-projection resonance

__device__ __forceinline__ float f2tf32(float f) {
    unsigned r;
    asm("cvt.rna.tf32.f32 %0, %1;" : "=r"(r) : "f"(f));
    return __uint_as_float(r);
}

__device__ __forceinline__ void mma_tf32(float d[4], const unsigned a[4],
                                         unsigned b0, unsigned b1) {
    asm("mma.sync.aligned.m16n8k8.row.col.f32.tf32.tf32.f32 "
        "{%0,%1,%2,%3}, {%4,%5,%6,%7}, {%8,%9}, {%0,%1,%2,%3};"
        : "+f"(d[0]), "+f"(d[1]), "+f"(d[2]), "+f"(d[3])
        : "r"(a[0]), "r"(a[1]), "r"(a[2]), "r"(a[3]), "r"(b0), "r"(b1));
}

__device__ __forceinline__ void cp16(float* dst, const float* src) {
    unsigned d = (unsigned)__cvta_generic_to_shared(dst);
    asm volatile("cp.async.cg.shared.global [%0], [%1], 16;" :: "r"(d), "l"(src));
}

// ---------------- kernel 1: w = amp * cos(phase), stored transposed [h][o] ----------
__global__ void k_w(const float* __restrict__ pq, const float* __restrict__ aq,
                    const float* __restrict__ pk, const float* __restrict__ ak,
                    const float* __restrict__ pv, const float* __restrict__ av,
                    const float* __restrict__ po, const float* __restrict__ ao) {
    int i = blockIdx.x * blockDim.x + threadIdx.x;
    int o = i >> 5, h = i & 31;
    int j = h * Cdim + o;
    g_w[0][j] = aq[i] * cosf(pq[i]);
    g_w[1][j] = ak[i] * cosf(pk[i]);
    g_w[2][j] = av[i] * cosf(pv[i]);
    g_w[3][j] = ao[i] * cosf(po[i]);
}

// ---------------- kernel 2: transpose + stack bases ---------------------------------
__global__ void k_tr(const float* __restrict__ bq, const float* __restrict__ bk,
                     const float* __restrict__ bv, const float* __restrict__ bo) {
    int i = blockIdx.x * blockDim.x + threadIdx.x;
    int h = i >> 10, d = i & 1023;
    g_Bt[d*96 + h]      = bq[i];
    g_Bt[d*96 + 32 + h] = bk[i];
    g_Bt[d*96 + 64 + h] = bv[i];
    g_BoT[d*32 + h]     = bo[i];
}

// ---------------- kernel 3: R = x @ Bt  ([4096,1024] x [1024,96]) -------------------
// 16 tokens per block (64KB dyn smem), each thread: 4 tokens x 1 output column.
__global__ void __launch_bounds__(384) k_res96(const float* __restrict__ x) {
    extern __shared__ float xs[];     // [16][1024]
    int t0 = blockIdx.x * 16;
    const float4* xg = (const float4*)(x + (size_t)t0 * Cdim);
    float4* s4 = (float4*)xs;
    for (int i = threadIdx.x; i < 4096; i += 384) s4[i] = xg[i];
    __syncthreads();
    int j  = threadIdx.x % 96;
    int tg = threadIdx.x / 96;        // 0..3, four tokens each
    const float* xr0 = xs + (tg*4 + 0)*1024;
    const float* xr1 = xs + (tg*4 + 1)*1024;
    const float* xr2 = xs + (tg*4 + 2)*1024;
    const float* xr3 = xs + (tg*4 + 3)*1024;
    float a0 = 0.f, a1 = 0.f, a2 = 0.f, a3 = 0.f;
    #pragma unroll 8
    for (int i = 0; i < 1024; i++) {
        float b = g_Bt[i*96 + j];
        a0 += xr0[i] * b;
        a1 += xr1[i] * b;
        a2 += xr2[i] * b;
        a3 += xr3[i] * b;
    }
    g_R[(size_t)(t0 + tg*4    )*96 + j] = a0;
    g_R[(size_t)(t0 + tg*4 + 1)*96 + j] = a1;
    g_R[(size_t)(t0 + tg*4 + 2)*96 + j] = a2;
    g_R[(size_t)(t0 + tg*4 + 3)*96 + j] = a3;
}

// ---------------- kernel 6: Ro = att @ BoT ------------------------------------------
// 16 tokens per block (64KB dyn smem), each thread: 2 tokens x 1 harmonic.
__global__ void __launch_bounds__(256) k_res32() {
    extern __shared__ float xs[];     // [16][1024]
    int t0 = blockIdx.x * 16;
    const float4* xg = (const float4*)(g_att + (size_t)t0 * Cdim);
    float4* s4 = (float4*)xs;
    for (int i = threadIdx.x; i < 4096; i += 256) s4[i] = xg[i];
    __syncthreads();
    int h  = threadIdx.x & 31;
    int tg = threadIdx.x >> 5;        // 0..7, two tokens each
    const float* xr0 = xs + (tg*2    )*1024;
    const float* xr1 = xs + (tg*2 + 1)*1024;
    float a0 = 0.f, a1 = 0.f;
    #pragma unroll 8
    for (int i = 0; i < 1024; i++) {
        float b = g_BoT[i*32 + h];
        a0 += xr0[i] * b;
        a1 += xr1[i] * b;
    }
    g_Ro[(size_t)(t0 + tg*2    )*32 + h] = a0;
    g_Ro[(size_t)(t0 + tg*2 + 1)*32 + h] = a1;
}

// ---------------- kernel 4/7: expand resonance --------------------------------------
// 8 tokens per block, each thread 8x4 accumulator -> ~70 regs, 3-4 blocks/SM.
__global__ void __launch_bounds__(256) k_proj(int which, float* __restrict__ dout) {
    __shared__ float Rs[8][32];
    int t0 = blockIdx.x * 8;
    int tid = threadIdx.x;
    const float* Rsrc; int rstride, roff; const float* w; float* out;
    if (which < 3) { Rsrc = g_R;  rstride = 96; roff = which*32; w = g_w[which]; out = g_qkv[which]; }
    else           { Rsrc = g_Ro; rstride = 32; roff = 0;        w = g_w[3];     out = dout; }

    if (tid < 256) {
        int t = tid >> 5, h = tid & 31;
        Rs[t][h] = Rsrc[(size_t)(t0 + t)*rstride + roff + h];
    }
    __syncthreads();

    float acc[8][4];
    #pragma unroll
    for (int t = 0; t < 8; t++)
        #pragma unroll
        for (int j = 0; j < 4; j++) acc[t][j] = 0.f;

    #pragma unroll
    for (int h = 0; h < 32; h++) {
        float w0 = w[h*Cdim + tid      ];
        float w1 = w[h*Cdim + tid + 256];
        float w2 = w[h*Cdim + tid + 512];
        float w3 = w[h*Cdim + tid + 768];
        #pragma unroll
        for (int t = 0; t < 8; t++) {
            float r = Rs[t][h];
            acc[t][0] += r * w0;
            acc[t][1] += r * w1;
            acc[t][2] += r * w2;
            acc[t][3] += r * w3;
        }
    }
    #pragma unroll
    for (int t = 0; t < 8; t++) {
        float* op = out + (size_t)(t0 + t)*Cdim;
        op[tid      ] = acc[t][0];
        op[tid + 256] = acc[t][1];
        op[tid + 512] = acc[t][2];
        op[tid + 768] = acc[t][3];
    }
}

// ---------------- kernel 5: flash attention, tf32 mma.sync, cp.async double-buffer --
// grid (L/128, B*H), 256 threads = 8 warps, each warp owns 16 query rows.
// K/V land in smem as raw f32; HMMA tf32 truncates mantissa in HW.
#define SST 68
#define KVBUF (2*64*SST)
__global__ void __launch_bounds__(256, 2) k_attn() {
    extern __shared__ float smem[];
    float* QPs = smem;                 // [128][68]: Q (prologue) then P (warp-local)

    int qt = blockIdx.x;
    int bh = blockIdx.y;
    int b = bh >> 4, h = bh & 15;
    const float* __restrict__ Qg = g_qkv[0] + (size_t)b*Ls*Cdim + h*HD;
    const float* __restrict__ Kg = g_qkv[1] + (size_t)b*Ls*Cdim + h*HD;
    const float* __restrict__ Vg = g_qkv[2] + (size_t)b*Ls*Cdim + h*HD;
    float* __restrict__ Og = g_att + (size_t)b*Ls*Cdim + h*HD;

    int tid = threadIdx.x;
    int wid = tid >> 5, lane = tid & 31;
    int g = lane >> 2, c = lane & 3;
    int wr = wid * 16;
    const float scale = 0.125f;

    // issue K/V tile `kt` into buffer `buf` (2048 x 16B cp.async, 8 per thread)
    auto loadKV = [&](int kt, int buf) {
        float* Kb = smem + 128*SST + buf*KVBUF;
        float* Vb = Kb + 64*SST;
        #pragma unroll
        for (int u = 0; u < 8; u++) {
            int i = tid + u*256;       // 0..2047
            int m = i >> 10;           // 0 = K, 1 = V
            int j = i & 1023;
            int r = j >> 4, ch = j & 15;
            const float* src = (m ? Vg : Kg) + (size_t)(kt*64 + r)*Cdim + ch*4;
            float* dst = (m ? Vb : Kb) + r*SST + ch*4;
            cp16(dst, src);
        }
        asm volatile("cp.async.commit_group;");
    };

    loadKV(0, 0);

    // ---- prologue: Q tile -> smem (scaled, tf32 RNA), then to register frags ----
    for (int i = tid; i < 2048; i += 256) {
        int r = i >> 4, f4 = i & 15;
        float4 v = *(const float4*)(Qg + (size_t)(qt*128 + r)*Cdim + f4*4);
        float* dst = &QPs[r*SST + f4*4];
        dst[0] = f2tf32(v.x*scale); dst[1] = f2tf32(v.y*scale);
        dst[2] = f2tf32(v.z*scale); dst[3] = f2tf32(v.w*scale);
    }
    __syncthreads();

    unsigned qf[8][4];
    #pragma unroll
    for (int kg = 0; kg < 8; kg++) {
        qf[kg][0] = __float_as_uint(QPs[(wr+g  )*SST + kg*8 + c    ]);
        qf[kg][1] = __float_as_uint(QPs[(wr+g+8)*SST + kg*8 + c    ]);
        qf[kg][2] = __float_as_uint(QPs[(wr+g  )*SST + kg*8 + c + 4]);
        qf[kg][3] = __float_as_uint(QPs[(wr+g+8)*SST + kg*8 + c + 4]);
    }

    float m0 = -1e30f, m1 = -1e30f, l0 = 0.f, l1 = 0.f;
    float O[8][4];
    #pragma unroll
    for (int nt = 0; nt < 8; nt++)
        #pragma unroll
        for (int j = 0; j < 4; j++) O[nt][j] = 0.f;

    for (int kt = 0; kt < 32; kt++) {
        __syncthreads();   // all compute on buf[(kt+1)&1] (tile kt-1) finished
        if (kt + 1 < 32) {
            loadKV(kt + 1, (kt + 1) & 1);
            asm volatile("cp.async.wait_group 1;");   // tile kt landed
        } else {
            asm volatile("cp.async.wait_group 0;");
        }
        __syncthreads();

        const float* Ks = smem + 128*SST + (kt & 1)*KVBUF;
        const float* Vs = Ks + 64*SST;

        // ---- S = Q . K^T ----
        float S[8][4];
        #pragma unroll
        for (int nt = 0; nt < 8; nt++)
            #pragma unroll
            for (int j = 0; j < 4; j++) S[nt][j] = 0.f;

        #pragma unroll
        for (int kg = 0; kg < 8; kg++) {
            #pragma unroll
            for (int nt = 0; nt < 8; nt++) {
                unsigned b0 = __float_as_uint(Ks[(nt*8+g)*SST + kg*8 + c    ]);
                unsigned b1 = __float_as_uint(Ks[(nt*8+g)*SST + kg*8 + c + 4]);
                mma_tf32(S[nt], qf[kg], b0, b1);
            }
        }

        // ---- online softmax ----
        float mx0 = -1e30f, mx1 = -1e30f;
        #pragma unroll
        for (int nt = 0; nt < 8; nt++) {
            mx0 = fmaxf(mx0, fmaxf(S[nt][0], S[nt][1]));
            mx1 = fmaxf(mx1, fmaxf(S[nt][2], S[nt][3]));
        }
        mx0 = fmaxf(mx0, __shfl_xor_sync(0xffffffffu, mx0, 1));
        mx0 = fmaxf(mx0, __shfl_xor_sync(0xffffffffu, mx0, 2));
        mx1 = fmaxf(mx1, __shfl_xor_sync(0xffffffffu, mx1, 1));
        mx1 = fmaxf(mx1, __shfl_xor_sync(0xffffffffu, mx1, 2));

        float mn0 = fmaxf(m0, mx0), mn1 = fmaxf(m1, mx1);
        float a0 = __expf(m0 - mn0), a1 = __expf(m1 - mn1);
        m0 = mn0; m1 = mn1;

        float s0 = 0.f, s1 = 0.f;
        #pragma unroll
        for (int nt = 0; nt < 8; nt++) {
            S[nt][0] = __expf(S[nt][0] - mn0); s0 += S[nt][0];
            S[nt][1] = __expf(S[nt][1] - mn0); s0 += S[nt][1];
            S[nt][2] = __expf(S[nt][2] - mn1); s1 += S[nt][2];
            S[nt][3] = __expf(S[nt][3] - mn1); s1 += S[nt][3];
        }
        s0 += __shfl_xor_sync(0xffffffffu, s0, 1);
        s0 += __shfl_xor_sync(0xffffffffu, s0, 2);
        s1 += __shfl_xor_sync(0xffffffffu, s1, 1);
        s1 += __shfl_xor_sync(0xffffffffu, s1, 2);
        l0 = l0*a0 + s0;
        l1 = l1*a1 + s1;
        #pragma unroll
        for (int nt = 0; nt < 8; nt++) {
            O[nt][0] *= a0; O[nt][1] *= a0;
            O[nt][2] *= a1; O[nt][3] *= a1;
        }

        // ---- store P (warp-local rows; HW truncation to tf32 in the MMA) ----
        #pragma unroll
        for (int nt = 0; nt < 8; nt++) {
            QPs[(wr+g  )*SST + nt*8 + 2*c    ] = S[nt][0];
            QPs[(wr+g  )*SST + nt*8 + 2*c + 1] = S[nt][1];
            QPs[(wr+g+8)*SST + nt*8 + 2*c    ] = S[nt][2];
            QPs[(wr+g+8)*SST + nt*8 + 2*c + 1] = S[nt][3];
        }
        __syncwarp();

        // ---- O += P . V ----
        #pragma unroll
        for (int kg = 0; kg < 8; kg++) {
            unsigned pf[4];
            pf[0] = __float_as_uint(QPs[(wr+g  )*SST + kg*8 + c    ]);
            pf[1] = __float_as_uint(QPs[(wr+g+8)*SST + kg*8 + c    ]);
            pf[2] = __float_as_uint(QPs[(wr+g  )*SST + kg*8 + c + 4]);
            pf[3] = __float_as_uint(QPs[(wr+g+8)*SST + kg*8 + c + 4]);
            #pragma unroll
            for (int nt = 0; nt < 8; nt++) {
                unsigned b0 = __float_as_uint(Vs[(kg*8 + c    )*SST + nt*8 + g]);
                unsigned b1 = __float_as_uint(Vs[(kg*8 + c + 4)*SST + nt*8 + g]);
                mma_tf32(O[nt], pf, b0, b1);
            }
        }
        __syncwarp();   // PV reads done before next-iteration P overwrite
    }

    // ---- epilogue ----
    float i0 = 1.f / l0, i1 = 1.f / l1;
    #pragma unroll
    for (int nt = 0; nt < 8; nt++) {
        float2 o0 = make_float2(O[nt][0]*i0, O[nt][1]*i0);
        float2 o1 = make_float2(O[nt][2]*i1, O[nt][3]*i1);
        *(float2*)(Og + (size_t)(qt*128 + wr + g    )*Cdim + nt*8 + 2*c) = o0;
        *(float2*)(Og + (size_t)(qt*128 + wr + g + 8)*Cdim + nt*8 + 2*c) = o1;
    }
}

// ---------------- launch -------------------------------------------------------------
extern "C" void kernel_launch(void* const* d_in, const int* in_sizes, int n_in,
                              void* d_out, int out_size) {
    const float* x  = (const float*)d_in[0];
    const float* bq = (const float*)d_in[1];
    const float* pq = (const float*)d_in[2];
    const float* aq = (const float*)d_in[3];
    const float* bk = (const float*)d_in[4];
    const float* pk = (const float*)d_in[5];
    const float* ak = (const float*)d_in[6];
    const float* bv = (const float*)d_in[7];
    const float* pv = (const float*)d_in[8];
    const float* av = (const float*)d_in[9];
    const float* bo = (const float*)d_in[10];
    const float* po = (const float*)d_in[11];
    const float* ao = (const float*)d_in[12];
    float* out = (float*)d_out;

    const int ATTN_SMEM = (128*SST + 2*KVBUF) * 4;   // 104448 B

    static bool attr_set = false;
    if (!attr_set) {
        cudaFuncSetAttribute(k_attn,  cudaFuncAttributeMaxDynamicSharedMemorySize, ATTN_SMEM);
        cudaFuncSetAttribute(k_res96, cudaFuncAttributeMaxDynamicSharedMemorySize, 65536);
        cudaFuncSetAttribute(k_res32, cudaFuncAttributeMaxDynamicSharedMemorySize, 65536);
        attr_set = true;
    }

    k_w  <<<128, 256>>>(pq, aq, pk, ak, pv, av, po, ao);
    k_tr <<<128, 256>>>(bq, bk, bv, bo);
    k_res96<<<TOK/16, 384, 65536>>>(x);
    k_proj<<<TOK/8, 256>>>(0, out);
    k_proj<<<TOK/8, 256>>>(1, out);
    k_proj<<<TOK/8, 256>>>(2, out);
    k_attn<<<dim3(Ls/128, Bsz*NH), 256, ATTN_SMEM>>>();
    k_res32<<<TOK/16, 256, 65536>>>();
    k_proj<<<TOK/8, 256>>>(3, out);
}

// round 6
// speedup vs baseline: 2.4445x; 1.1298x over previous
#include <cuda_runtime.h>
#include <math.h>

#define Bsz   2
#define Ls    2048
#define Cdim  1024
#define NH    16
#define HD    64
#define HARM  32
#define TOK   (Bsz*Ls)   // 4096

// ---------------- device scratch ----------------------------------------------------
__device__ float g_w[4][HARM*Cdim];      // w transposed: [h][o]
__device__ float g_Bt[Cdim*96];          // stacked qkv basis, transposed
__device__ float g_BoT[Cdim*HARM];       // basis_o transposed
__device__ float g_R[TOK*96];            // qkv resonances
__device__ float g_qkv[3][TOK*Cdim];     // q, k(d-permuted), v in [B,L,C] layout
__device__ float g_att[TOK*Cdim];        // attention output [B,L,C]
__device__ float g_Ro[TOK*HARM];         // output-projection resonance

__device__ __forceinline__ float f2tf32(float f) {
    unsigned r;
    asm("cvt.rna.tf32.f32 %0, %1;" : "=r"(r) : "f"(f));
    return __uint_as_float(r);
}

__device__ __forceinline__ void mma_tf32(float d[4], const unsigned a[4],
                                         unsigned b0, unsigned b1) {
    asm("mma.sync.aligned.m16n8k8.row.col.f32.tf32.tf32.f32 "
        "{%0,%1,%2,%3}, {%4,%5,%6,%7}, {%8,%9}, {%0,%1,%2,%3};"
        : "+f"(d[0]), "+f"(d[1]), "+f"(d[2]), "+f"(d[3])
        : "r"(a[0]), "r"(a[1]), "r"(a[2]), "r"(a[3]), "r"(b0), "r"(b1));
}

__device__ __forceinline__ void cp16(float* dst, const float* src) {
    unsigned d = (unsigned)__cvta_generic_to_shared(dst);
    asm volatile("cp.async.cg.shared.global [%0], [%1], 16;" :: "r"(d), "l"(src));
}

// ---------------- kernel 1: w = amp * cos(phase), stored transposed [h][o] ----------
__global__ void k_w(const float* __restrict__ pq, const float* __restrict__ aq,
                    const float* __restrict__ pk, const float* __restrict__ ak,
                    const float* __restrict__ pv, const float* __restrict__ av,
                    const float* __restrict__ po, const float* __restrict__ ao) {
    int i = blockIdx.x * blockDim.x + threadIdx.x;
    int o = i >> 5, h = i & 31;
    int j = h * Cdim + o;
    g_w[0][j] = aq[i] * cosf(pq[i]);
    g_w[1][j] = ak[i] * cosf(pk[i]);
    g_w[2][j] = av[i] * cosf(pv[i]);
    g_w[3][j] = ao[i] * cosf(po[i]);
}

// ---------------- kernel 2: transpose + stack bases ---------------------------------
__global__ void k_tr(const float* __restrict__ bq, const float* __restrict__ bk,
                     const float* __restrict__ bv, const float* __restrict__ bo) {
    int i = blockIdx.x * blockDim.x + threadIdx.x;
    int h = i >> 10, d = i & 1023;
    g_Bt[d*96 + h]      = bq[i];
    g_Bt[d*96 + 32 + h] = bk[i];
    g_Bt[d*96 + 64 + h] = bv[i];
    g_BoT[d*32 + h]     = bo[i];
}

// ---------------- kernel 3: R = x @ Bt  ([4096,1024] x [1024,96]) -------------------
__global__ void __launch_bounds__(384) k_res96(const float* __restrict__ x) {
    extern __shared__ float xs[];     // [16][1024]
    int t0 = blockIdx.x * 16;
    const float4* xg = (const float4*)(x + (size_t)t0 * Cdim);
    float4* s4 = (float4*)xs;
    for (int i = threadIdx.x; i < 4096; i += 384) s4[i] = xg[i];
    __syncthreads();
    int j  = threadIdx.x % 96;
    int tg = threadIdx.x / 96;
    const float* xr0 = xs + (tg*4 + 0)*1024;
    const float* xr1 = xs + (tg*4 + 1)*1024;
    const float* xr2 = xs + (tg*4 + 2)*1024;
    const float* xr3 = xs + (tg*4 + 3)*1024;
    float a0 = 0.f, a1 = 0.f, a2 = 0.f, a3 = 0.f;
    #pragma unroll 8
    for (int i = 0; i < 1024; i++) {
        float b = g_Bt[i*96 + j];
        a0 += xr0[i] * b;
        a1 += xr1[i] * b;
        a2 += xr2[i] * b;
        a3 += xr3[i] * b;
    }
    g_R[(size_t)(t0 + tg*4    )*96 + j] = a0;
    g_R[(size_t)(t0 + tg*4 + 1)*96 + j] = a1;
    g_R[(size_t)(t0 + tg*4 + 2)*96 + j] = a2;
    g_R[(size_t)(t0 + tg*4 + 3)*96 + j] = a3;
}

// ---------------- kernel 6: Ro = att @ BoT ------------------------------------------
__global__ void __launch_bounds__(256) k_res32() {
    extern __shared__ float xs[];     // [16][1024]
    int t0 = blockIdx.x * 16;
    const float4* xg = (const float4*)(g_att + (size_t)t0 * Cdim);
    float4* s4 = (float4*)xs;
    for (int i = threadIdx.x; i < 4096; i += 256) s4[i] = xg[i];
    __syncthreads();
    int h  = threadIdx.x & 31;
    int tg = threadIdx.x >> 5;
    const float* xr0 = xs + (tg*2    )*1024;
    const float* xr1 = xs + (tg*2 + 1)*1024;
    float a0 = 0.f, a1 = 0.f;
    #pragma unroll 8
    for (int i = 0; i < 1024; i++) {
        float b = g_BoT[i*32 + h];
        a0 += xr0[i] * b;
        a1 += xr1[i] * b;
    }
    g_Ro[(size_t)(t0 + tg*2    )*32 + h] = a0;
    g_Ro[(size_t)(t0 + tg*2 + 1)*32 + h] = a1;
}

// ---------------- kernel 4/7: expand resonance --------------------------------------
// Each thread owns 4 consecutive columns (float4 w loads/stores), 8 tokens.
// K output (which==1) is stored with the within-8 d-permutation r -> (r<4 ? 2r : 2r-7)
// so k_attn's B-fragments (d = c, c+4) sit adjacent -> single LDS.64.
__global__ void __launch_bounds__(256) k_proj(int which, float* __restrict__ dout) {
    __shared__ float Rs[8][32];
    int t0 = blockIdx.x * 8;
    int tid = threadIdx.x;
    const float* Rsrc; int rstride, roff; const float* w; float* out;
    if (which < 3) { Rsrc = g_R;  rstride = 96; roff = which*32; w = g_w[which]; out = g_qkv[which]; }
    else           { Rsrc = g_Ro; rstride = 32; roff = 0;        w = g_w[3];     out = dout; }

    {
        int t = tid >> 5, h = tid & 31;
        Rs[t][h] = Rsrc[(size_t)(t0 + t)*rstride + roff + h];
    }
    __syncthreads();

    int c0 = tid * 4;
    float acc[8][4];
    #pragma unroll
    for (int t = 0; t < 8; t++)
        #pragma unroll
        for (int j = 0; j < 4; j++) acc[t][j] = 0.f;

    #pragma unroll
    for (int h = 0; h < 32; h++) {
        float4 w4 = *(const float4*)&w[h*Cdim + c0];
        #pragma unroll
        for (int t = 0; t < 8; t++) {
            float r = Rs[t][h];
            acc[t][0] += r * w4.x;
            acc[t][1] += r * w4.y;
            acc[t][2] += r * w4.z;
            acc[t][3] += r * w4.w;
        }
    }
    if (which == 1) {
        // permuted scalar stores: col c0+j -> (col&~7) + 2*j + (tid&1)
        int base = (c0 & ~7) + (tid & 1);
        #pragma unroll
        for (int t = 0; t < 8; t++) {
            float* op = out + (size_t)(t0 + t)*Cdim;
            #pragma unroll
            for (int j = 0; j < 4; j++) op[base + 2*j] = acc[t][j];
        }
    } else {
        #pragma unroll
        for (int t = 0; t < 8; t++) {
            float4 v = make_float4(acc[t][0], acc[t][1], acc[t][2], acc[t][3]);
            *(float4*)(out + (size_t)(t0 + t)*Cdim + c0) = v;
        }
    }
}

// ---------------- kernel 5: flash attention, tf32 mma.sync --------------------------
// SST=72 (== 8 mod 32): conflict-free V scalar loads and 64-bit K/P loads.
#define SST 72
#define KVBUF (2*64*SST)
__global__ void __launch_bounds__(256, 2) k_attn() {
    extern __shared__ float smem[];
    float* QPs = smem;                 // [128][72]: Q (prologue) then P (warp-local)

    int qt = blockIdx.x;
    int bh = blockIdx.y;
    int b = bh >> 4, h = bh & 15;
    const float* __restrict__ Qg = g_qkv[0] + (size_t)b*Ls*Cdim + h*HD;
    const float* __restrict__ Kg = g_qkv[1] + (size_t)b*Ls*Cdim + h*HD;
    const float* __restrict__ Vg = g_qkv[2] + (size_t)b*Ls*Cdim + h*HD;
    float* __restrict__ Og = g_att + (size_t)b*Ls*Cdim + h*HD;

    int tid = threadIdx.x;
    int wid = tid >> 5, lane = tid & 31;
    int g = lane >> 2, c = lane & 3;
    int wr = wid * 16;
    const float scale = 0.125f;

    auto loadKV = [&](int kt, int buf) {
        float* Kb = smem + 128*SST + buf*KVBUF;
        float* Vb = Kb + 64*SST;
        #pragma unroll
        for (int u = 0; u < 8; u++) {
            int i = tid + u*256;       // 0..2047
            int m = i >> 10;           // 0 = K, 1 = V
            int j = i & 1023;
            int r = j >> 4, ch = j & 15;
            const float* src = (m ? Vg : Kg) + (size_t)(kt*64 + r)*Cdim + ch*4;
            float* dst = (m ? Vb : Kb) + r*SST + ch*4;
            cp16(dst, src);
        }
        asm volatile("cp.async.commit_group;");
    };

    loadKV(0, 0);

    // ---- prologue: Q tile -> smem (scaled, tf32 RNA), then to register frags ----
    for (int i = tid; i < 2048; i += 256) {
        int r = i >> 4, f4 = i & 15;
        float4 v = *(const float4*)(Qg + (size_t)(qt*128 + r)*Cdim + f4*4);
        float* dst = &QPs[r*SST + f4*4];
        dst[0] = f2tf32(v.x*scale); dst[1] = f2tf32(v.y*scale);
        dst[2] = f2tf32(v.z*scale); dst[3] = f2tf32(v.w*scale);
    }
    __syncthreads();

    unsigned qf[8][4];
    #pragma unroll
    for (int kg = 0; kg < 8; kg++) {
        qf[kg][0] = __float_as_uint(QPs[(wr+g  )*SST + kg*8 + c    ]);
        qf[kg][1] = __float_as_uint(QPs[(wr+g+8)*SST + kg*8 + c    ]);
        qf[kg][2] = __float_as_uint(QPs[(wr+g  )*SST + kg*8 + c + 4]);
        qf[kg][3] = __float_as_uint(QPs[(wr+g+8)*SST + kg*8 + c + 4]);
    }

    float m0 = -1e30f, m1 = -1e30f, l0 = 0.f, l1 = 0.f;
    float O[8][4];
    #pragma unroll
    for (int nt = 0; nt < 8; nt++)
        #pragma unroll
        for (int j = 0; j < 4; j++) O[nt][j] = 0.f;

    // P store positions for keys 2c, 2c+1 under perm r -> (r<4 ? 2r : 2r-7)
    int pos0 = (c < 2) ? 4*c : 4*c - 7;

    for (int kt = 0; kt < 32; kt++) {
        __syncthreads();
        if (kt + 1 < 32) {
            loadKV(kt + 1, (kt + 1) & 1);
            asm volatile("cp.async.wait_group 1;");
        } else {
            asm volatile("cp.async.wait_group 0;");
        }
        __syncthreads();

        const float* Ks = smem + 128*SST + (kt & 1)*KVBUF;
        const float* Vs = Ks + 64*SST;

        // ---- S = Q . K^T (K stored d-permuted -> LDS.64 B-frags) ----
        float S[8][4];
        #pragma unroll
        for (int nt = 0; nt < 8; nt++)
            #pragma unroll
            for (int j = 0; j < 4; j++) S[nt][j] = 0.f;

        #pragma unroll
        for (int kg = 0; kg < 8; kg++) {
            #pragma unroll
            for (int nt = 0; nt < 8; nt++) {
                float2 kv2 = *(const float2*)&Ks[(nt*8+g)*SST + kg*8 + 2*c];
                mma_tf32(S[nt], qf[kg],
                         __float_as_uint(kv2.x), __float_as_uint(kv2.y));
            }
        }

        // ---- online softmax ----
        float mx0 = -1e30f, mx1 = -1e30f;
        #pragma unroll
        for (int nt = 0; nt < 8; nt++) {
            mx0 = fmaxf(mx0, fmaxf(S[nt][0], S[nt][1]));
            mx1 = fmaxf(mx1, fmaxf(S[nt][2], S[nt][3]));
        }
        mx0 = fmaxf(mx0, __shfl_xor_sync(0xffffffffu, mx0, 1));
        mx0 = fmaxf(mx0, __shfl_xor_sync(0xffffffffu, mx0, 2));
        mx1 = fmaxf(mx1, __shfl_xor_sync(0xffffffffu, mx1, 1));
        mx1 = fmaxf(mx1, __shfl_xor_sync(0xffffffffu, mx1, 2));

        float mn0 = fmaxf(m0, mx0), mn1 = fmaxf(m1, mx1);
        float a0 = __expf(m0 - mn0), a1 = __expf(m1 - mn1);
        m0 = mn0; m1 = mn1;

        float s0 = 0.f, s1 = 0.f;
        #pragma unroll
        for (int nt = 0; nt < 8; nt++) {
            S[nt][0] = __expf(S[nt][0] - mn0); s0 += S[nt][0];
            S[nt][1] = __expf(S[nt][1] - mn0); s0 += S[nt][1];
            S[nt][2] = __expf(S[nt][2] - mn1); s1 += S[nt][2];
            S[nt][3] = __expf(S[nt][3] - mn1); s1 += S[nt][3];
        }
        s0 += __shfl_xor_sync(0xffffffffu, s0, 1);
        s0 += __shfl_xor_sync(0xffffffffu, s0, 2);
        s1 += __shfl_xor_sync(0xffffffffu, s1, 1);
        s1 += __shfl_xor_sync(0xffffffffu, s1, 2);
        l0 = l0*a0 + s0;
        l1 = l1*a1 + s1;
        #pragma unroll
        for (int nt = 0; nt < 8; nt++) {
            O[nt][0] *= a0; O[nt][1] *= a0;
            O[nt][2] *= a1; O[nt][3] *= a1;
        }

        // ---- store P at permuted key positions (pos0, pos0+2) ----
        #pragma unroll
        for (int nt = 0; nt < 8; nt++) {
            QPs[(wr+g  )*SST + nt*8 + pos0    ] = S[nt][0];
            QPs[(wr+g  )*SST + nt*8 + pos0 + 2] = S[nt][1];
            QPs[(wr+g+8)*SST + nt*8 + pos0    ] = S[nt][2];
            QPs[(wr+g+8)*SST + nt*8 + pos0 + 2] = S[nt][3];
        }
        __syncwarp();

        // ---- O += P . V (P A-frags via LDS.64 at permuted positions) ----
        #pragma unroll
        for (int kg = 0; kg < 8; kg++) {
            float2 p0 = *(const float2*)&QPs[(wr+g  )*SST + kg*8 + 2*c];
            float2 p1 = *(const float2*)&QPs[(wr+g+8)*SST + kg*8 + 2*c];
            unsigned pf[4] = { __float_as_uint(p0.x), __float_as_uint(p1.x),
                               __float_as_uint(p0.y), __float_as_uint(p1.y) };
            #pragma unroll
            for (int nt = 0; nt < 8; nt++) {
                unsigned b0 = __float_as_uint(Vs[(kg*8 + c    )*SST + nt*8 + g]);
                unsigned b1 = __float_as_uint(Vs[(kg*8 + c + 4)*SST + nt*8 + g]);
                mma_tf32(O[nt], pf, b0, b1);
            }
        }
        __syncwarp();
    }

    // ---- epilogue ----
    float i0 = 1.f / l0, i1 = 1.f / l1;
    #pragma unroll
    for (int nt = 0; nt < 8; nt++) {
        float2 o0 = make_float2(O[nt][0]*i0, O[nt][1]*i0);
        float2 o1 = make_float2(O[nt][2]*i1, O[nt][3]*i1);
        *(float2*)(Og + (size_t)(qt*128 + wr + g    )*Cdim + nt*8 + 2*c) = o0;
        *(float2*)(Og + (size_t)(qt*128 + wr + g + 8)*Cdim + nt*8 + 2*c) = o1;
    }
}

// ---------------- launch -------------------------------------------------------------
extern "C" void kernel_launch(void* const* d_in, const int* in_sizes, int n_in,
                              void* d_out, int out_size) {
    const float* x  = (const float*)d_in[0];
    const float* bq = (const float*)d_in[1];
    const float* pq = (const float*)d_in[2];
    const float* aq = (const float*)d_in[3];
    const float* bk = (const float*)d_in[4];
    const float* pk = (const float*)d_in[5];
    const float* ak = (const float*)d_in[6];
    const float* bv = (const float*)d_in[7];
    const float* pv = (const float*)d_in[8];
    const float* av = (const float*)d_in[9];
    const float* bo = (const float*)d_in[10];
    const float* po = (const float*)d_in[11];
    const float* ao = (const float*)d_in[12];
    float* out = (float*)d_out;

    const int ATTN_SMEM = (128*SST + 2*KVBUF) * 4;   // 110592 B

    static bool attr_set = false;
    if (!attr_set) {
        cudaFuncSetAttribute(k_attn,  cudaFuncAttributeMaxDynamicSharedMemorySize, ATTN_SMEM);
        cudaFuncSetAttribute(k_res96, cudaFuncAttributeMaxDynamicSharedMemorySize, 65536);
        cudaFuncSetAttribute(k_res32, cudaFuncAttributeMaxDynamicSharedMemorySize, 65536);
        attr_set = true;
    }

    k_w  <<<128, 256>>>(pq, aq, pk, ak, pv, av, po, ao);
    k_tr <<<128, 256>>>(bq, bk, bv, bo);
    k_res96<<<TOK/16, 384, 65536>>>(x);
    k_proj<<<TOK/8, 256>>>(0, out);
    k_proj<<<TOK/8, 256>>>(1, out);
    k_proj<<<TOK/8, 256>>>(2, out);
    k_attn<<<dim3(Ls/128, Bsz*NH), 256, ATTN_SMEM>>>();
    k_res32<<<TOK/16, 256, 65536>>>();
    k_proj<<<TOK/8, 256>>>(3, out);
}